// round 3
// baseline (speedup 1.0000x reference)
#include <cuda_runtime.h>

// FisherLayer: N=8192 rows, D=256 dims, K=32 components.
// out[0:K*D]     = mean_n gamma[n,k]*(y1^2-1)/sqrt(2)
// out[K*D:2*K*D] = mean_n gamma[n,k]*y1
// with y1 = w*(x+b), gamma = softmax_k(-0.5*sum_d y1^2).
//
// Factored form:
//   y4[n,k]   = -0.5*( sum_d w2*x^2 + sum_d (2*w2*b)*x + c_k ),  c_k = sum_d w2*b^2
//   S0[k]     = sum_n gamma,  Sx[k,d] = sum_n gamma*x,  Sx2[k,d] = sum_n gamma*x^2
//   out_mu    = w*(Sx + b*S0)/N
//   out_sigma = (w2*(Sx2 + 2*b*Sx + b^2*S0) - S0) / (sqrt(2)*N)

#define NROWS 8192
#define DD    256
#define KK    32
#define GRID_MAIN 148

typedef unsigned long long u64;

// device scratch (allowed: static __device__ arrays)
__device__ __align__(16) u64    g_atu[DD * KK];   // packed (w2, 2*w2*b), index d*K + k
__device__ float                g_c[KK];
__device__ __align__(16) float2 g_Sacc[KK * DD];  // (Sx2, Sx), index k*D + d
__device__ float                g_S0[KK];

__device__ __forceinline__ u64 pack2(float lo, float hi) {
    u64 r; asm("mov.b64 %0, {%1, %2};" : "=l"(r) : "f"(lo), "f"(hi)); return r;
}
__device__ __forceinline__ float2 unpack2(u64 v) {
    float2 f; asm("mov.b64 {%0, %1}, %2;" : "=f"(f.x), "=f"(f.y) : "l"(v)); return f;
}
__device__ __forceinline__ u64 fma2(u64 a, u64 b, u64 c) {
    u64 d; asm("fma.rn.f32x2 %0, %1, %2, %3;" : "=l"(d) : "l"(a), "l"(b), "l"(c)); return d;
}

// ---------------- prep: params + zero accumulators ----------------
__global__ void fisher_prep(const float* __restrict__ w, const float* __restrict__ b) {
    int k = blockIdx.x;        // 0..31
    int d = threadIdx.x;       // 0..255
    float wv = w[k * DD + d];
    float bv = b[k * DD + d];
    float w2 = wv * wv;
    g_atu[d * KK + k] = pack2(w2, 2.0f * w2 * bv);   // (a, u) pairs with (x^2, x)
    g_Sacc[k * DD + d] = make_float2(0.0f, 0.0f);

    // block-reduce c_k = sum_d w2*b^2
    float cp = w2 * bv * bv;
    #pragma unroll
    for (int o = 16; o; o >>= 1) cp += __shfl_xor_sync(0xffffffffu, cp, o);
    __shared__ float red[8];
    if ((d & 31) == 0) red[d >> 5] = cp;
    __syncthreads();
    if (d < 8) {
        float v = red[d];
        #pragma unroll
        for (int o = 4; o; o >>= 1) v += __shfl_xor_sync(0xffu, v, o, 8);
        if (d == 0) { g_c[k] = v; g_S0[k] = 0.0f; }
    }
}

// ---------------- main: persistent blocks, batches of 8 rows ----------------
__global__ void __launch_bounds__(256, 1) fisher_main(const float* __restrict__ x) {
    __shared__ __align__(16) u64 s_xx2[2][8 * DD];   // (x^2, x) per [r*D + d], double-buffered
    __shared__ __align__(16) u64 s_gamma2[8 * KK];   // (g, g) per [r*K + k]
    __shared__ float s_part[8 * 256];                // y4 partials: [slice_warp][r*32 + k]
    __shared__ float s_s0[8 * KK];

    const int tid  = threadIdx.x;
    const int wrp  = tid >> 5;   // warp id = d-slice (phase A) / softmax row
    const int lane = tid & 31;   // lane = k (phase A)

    // phase-A params in registers: slice d in [wrp*32, wrp*32+32), column k=lane
    u64 atu[32];
    #pragma unroll
    for (int j = 0; j < 32; j++) atu[j] = g_atu[(wrp * 32 + j) * KK + lane];
    const float c_reg = g_c[lane];

    // phase-B accumulators: thread owns d = tid; (Sx2, Sx) per k
    u64 accB[32];
    #pragma unroll
    for (int k = 0; k < 32; k++) accB[k] = 0ull;
    float s0acc = 0.0f;

    const int NBATCH = NROWS / 8;   // 1024
    int batch = blockIdx.x;
    bool have = batch < NBATCH;

    // preload first batch (8 coalesced LDG per thread)
    float xr[8];
    if (have) {
        const float* xb = x + (size_t)batch * 8 * DD;
        #pragma unroll
        for (int r = 0; r < 8; r++) xr[r] = xb[r * DD + tid];
    }

    int bufsel = 0;
    while (have) {
        u64* buf = s_xx2[bufsel];
        #pragma unroll
        for (int r = 0; r < 8; r++) buf[r * DD + tid] = pack2(xr[r] * xr[r], xr[r]);

        // prefetch next batch (hidden under compute)
        int nbatch = batch + GRID_MAIN;
        bool nhave = nbatch < NBATCH;
        if (nhave) {
            const float* xb = x + (size_t)nbatch * 8 * DD;
            #pragma unroll
            for (int r = 0; r < 8; r++) xr[r] = xb[r * DD + tid];
        }
        __syncthreads();

        // ---- phase A: y4 partial over this warp's d-slice, all 8 rows ----
        u64 accA[8];
        #pragma unroll
        for (int r = 0; r < 8; r++) accA[r] = 0ull;
        #pragma unroll
        for (int j = 0; j < 32; j += 2) {
            const int d0 = wrp * 32 + j;
            #pragma unroll
            for (int r = 0; r < 8; r++) {
                ulonglong2 v = *reinterpret_cast<const ulonglong2*>(&buf[r * DD + d0]);
                accA[r] = fma2(atu[j],     v.x, accA[r]);
                accA[r] = fma2(atu[j + 1], v.y, accA[r]);
            }
        }
        #pragma unroll
        for (int r = 0; r < 8; r++) {
            float2 p = unpack2(accA[r]);
            s_part[wrp * 256 + r * 32 + lane] = p.x + p.y;
        }
        __syncthreads();

        // ---- reduce slices + softmax: warp `wrp` handles row r = wrp ----
        {
            float y = 0.0f;
            #pragma unroll
            for (int j = 0; j < 8; j++) y += s_part[j * 256 + wrp * 32 + lane];
            y = -0.5f * (y + c_reg);
            float m = y;
            #pragma unroll
            for (int o = 16; o; o >>= 1) m = fmaxf(m, __shfl_xor_sync(0xffffffffu, m, o));
            float e = __expf(y - m);
            float s = e;
            #pragma unroll
            for (int o = 16; o; o >>= 1) s += __shfl_xor_sync(0xffffffffu, s, o);
            float g = e / s;
            s0acc += g;
            s_gamma2[wrp * KK + lane] = pack2(g, g);
        }
        __syncthreads();

        // ---- phase B: thread owns column d=tid; accumulate (Sx2, Sx) per k ----
        #pragma unroll
        for (int r = 0; r < 8; r++) {
            u64 xv = buf[r * DD + tid];
            #pragma unroll
            for (int k = 0; k < 32; k += 2) {
                ulonglong2 gg = *reinterpret_cast<const ulonglong2*>(&s_gamma2[r * KK + k]);
                accB[k]     = fma2(gg.x, xv, accB[k]);
                accB[k + 1] = fma2(gg.y, xv, accB[k + 1]);
            }
        }

        batch = nbatch;
        have = nhave;
        bufsel ^= 1;
    }

    // ---- S0 combine across warps, then global atomics ----
    __syncthreads();
    s_s0[wrp * KK + lane] = s0acc;
    __syncthreads();
    if (wrp == 0) {
        float v = 0.0f;
        #pragma unroll
        for (int j = 0; j < 8; j++) v += s_s0[j * KK + lane];
        atomicAdd(&g_S0[lane], v);
    }
    #pragma unroll
    for (int k = 0; k < 32; k++) {
        float2 p = unpack2(accB[k]);
        atomicAdd(&g_Sacc[k * DD + tid].x, p.x);   // Sx2
        atomicAdd(&g_Sacc[k * DD + tid].y, p.y);   // Sx
    }
}

// ---------------- finalize ----------------
__global__ void fisher_fin(const float* __restrict__ w, const float* __restrict__ b,
                           float* __restrict__ out) {
    int idx = blockIdx.x * 256 + threadIdx.x;   // 0..8191, block == k
    int k = idx >> 8;
    float2 S  = g_Sacc[idx];        // (Sx2, Sx)
    float  S0 = g_S0[k];
    float  wv = w[idx], bv = b[idx];
    float  w2 = wv * wv;
    const float invN   = 1.0f / (float)NROWS;
    const float invNs2 = invN * 0.70710678118654752440f;   // 1/(N*sqrt(2))

    float mu  = wv * (S.y + bv * S0) * invN;
    float Ey2 = w2 * (S.x + 2.0f * bv * S.y + bv * bv * S0);
    float sig = (Ey2 - S0) * invNs2;

    out[idx]           = sig;   // sigma_part
    out[KK * DD + idx] = mu;    // mu_part
}

extern "C" void kernel_launch(void* const* d_in, const int* in_sizes, int n_in,
                              void* d_out, int out_size) {
    const float* x = (const float*)d_in[0];
    const float* w = (const float*)d_in[1];
    const float* b = (const float*)d_in[2];
    float* out = (float*)d_out;
    (void)in_sizes; (void)n_in; (void)out_size;

    fisher_prep<<<KK, 256>>>(w, b);
    fisher_main<<<GRID_MAIN, 256>>>(x);
    fisher_fin<<<KK, 256>>>(w, b, out);
}